// round 13
// baseline (speedup 1.0000x reference)
#include <cuda_runtime.h>
#include <cuda_fp16.h>
#include <cstdint>
#include <math.h>

#define D_MODEL 1024
#define HIDDEN  4096
#define NEXP    8
#define NSH     2
#define NTOK    4096
#define CAP     4096
#define NZ      (NEXP + NSH)
#define NSLOT   16384

// ---------------- device scratch (static; zero runtime allocation) ----------------
__device__ int   g_cnt[NEXP];
__device__ int   g_slot_tok[NEXP][CAP];
__device__ float g_slot_w[NEXP][CAP];
__device__ int   g_tok_e[NTOK][2];
__device__ float g_tok_w[NTOK][2];

__device__ __align__(16) __half g_xh[(size_t)NTOK * D_MODEL];            // x fp16
__device__ __align__(16) __half g_w1t[(size_t)NZ * HIDDEN * D_MODEL];    // W1^T fp16 [z][H][D]
__device__ __align__(16) __half g_w2t[(size_t)NZ * D_MODEL * HIDDEN];    // W2^T fp16 [z][D][H]
__device__ __align__(16) __half g_h[(size_t)NSLOT * HIDDEN];             // hidden acts fp16

__device__ __forceinline__ float gelu_exact(float v) {
    return 0.5f * v * (1.0f + erff(v * 0.70710678118654752440f));
}

// ---------------- PTX helpers ----------------
__device__ __forceinline__ uint32_t smem_u32(const void* p) {
    uint32_t a;
    asm("{ .reg .u64 t; cvta.to.shared.u64 t, %1; cvt.u32.u64 %0, t; }" : "=r"(a) : "l"(p));
    return a;
}
__device__ __forceinline__ void cp16(uint32_t dst, const void* src) {
    asm volatile("cp.async.cg.shared.global [%0], [%1], 16;\n" :: "r"(dst), "l"(src) : "memory");
}
#define CP_COMMIT() asm volatile("cp.async.commit_group;\n" ::: "memory")
template<int N> __device__ __forceinline__ void cp_wait() {
    asm volatile("cp.async.wait_group %0;\n" :: "n"(N) : "memory");
}
__device__ __forceinline__ void ldsm4(uint32_t& r0, uint32_t& r1, uint32_t& r2, uint32_t& r3,
                                      uint32_t addr) {
    asm volatile("ldmatrix.sync.aligned.m8n8.x4.shared.b16 {%0,%1,%2,%3}, [%4];"
                 : "=r"(r0), "=r"(r1), "=r"(r2), "=r"(r3) : "r"(addr));
}
__device__ __forceinline__ void mma_f16(float* d, const uint32_t* a, const uint32_t* b) {
    asm volatile(
        "mma.sync.aligned.m16n8k16.row.col.f32.f16.f16.f32 "
        "{%0,%1,%2,%3}, {%4,%5,%6,%7}, {%8,%9}, {%0,%1,%2,%3};"
        : "+f"(d[0]), "+f"(d[1]), "+f"(d[2]), "+f"(d[3])
        : "r"(a[0]), "r"(a[1]), "r"(a[2]), "r"(a[3]), "r"(b[0]), "r"(b[1]));
}

// ---------------- small kernels ----------------
__global__ void conv_x_kernel(const float* __restrict__ x) {
    if (blockIdx.x == 0 && threadIdx.x < NEXP) g_cnt[threadIdx.x] = 0;
    const int i = (blockIdx.x * 256 + threadIdx.x) * 4;
    const float4 v = *(const float4*)(x + i);
    *(__half2*)(g_xh + i)     = __floats2half2_rn(v.x, v.y);
    *(__half2*)(g_xh + i + 2) = __floats2half2_rn(v.z, v.w);
}

__global__ void router_kernel(const float* __restrict__ x,
                              const float* __restrict__ rW,
                              const float* __restrict__ rb) {
    const int t = blockIdx.x, tid = threadIdx.x;
    __shared__ float sg[128][NEXP];
    float acc[NEXP];
    #pragma unroll
    for (int e = 0; e < NEXP; e++) acc[e] = 0.0f;
    const float* xr = x + (size_t)t * D_MODEL;
    for (int d = tid; d < D_MODEL; d += 128) {
        const float xv = xr[d];
        const float* r = rW + (size_t)d * NEXP;
        #pragma unroll
        for (int e = 0; e < NEXP; e++) acc[e] += xv * r[e];
    }
    #pragma unroll
    for (int e = 0; e < NEXP; e++) sg[tid][e] = acc[e];
    __syncthreads();
    if (tid < NEXP) {
        float s = rb[tid];
        for (int i = 0; i < 128; i++) s += sg[i][tid];
        sg[0][tid] = s;
    }
    __syncthreads();
    if (tid == 0) {
        float g[NEXP];
        #pragma unroll
        for (int e = 0; e < NEXP; e++) g[e] = sg[0][e];
        int e0 = 0;
        #pragma unroll
        for (int e = 1; e < NEXP; e++) if (g[e] > g[e0]) e0 = e;
        int e1 = (e0 == 0) ? 1 : 0;
        #pragma unroll
        for (int e = 0; e < NEXP; e++) if (e != e0 && g[e] > g[e1]) e1 = e;
        const float p1 = expf(g[e1] - g[e0]);
        const float inv = 1.0f / (1.0f + p1);
        const float w0 = inv, w1 = p1 * inv;
        g_tok_e[t][0] = e0; g_tok_e[t][1] = e1;
        g_tok_w[t][0] = w0; g_tok_w[t][1] = w1;
        int p = atomicAdd(&g_cnt[e0], 1);
        g_slot_tok[e0][p] = t; g_slot_w[e0][p] = w0;
        p = atomicAdd(&g_cnt[e1], 1);
        g_slot_tok[e1][p] = t; g_slot_w[e1][p] = w1;
    }
}

__global__ void init_out_kernel(float* __restrict__ out,
                                const float* __restrict__ b2,
                                const float* __restrict__ sb2) {
    const int idx = blockIdx.x * 256 + threadIdx.x;
    if (idx >= NTOK * D_MODEL) return;
    const int t = idx >> 10, d = idx & 1023;
    float v = 0.5f * (sb2[d] + sb2[D_MODEL + d]);
    v += g_tok_w[t][0] * b2[(size_t)g_tok_e[t][0] * D_MODEL + d];
    v += g_tok_w[t][1] * b2[(size_t)g_tok_e[t][1] * D_MODEL + d];
    out[idx] = v;
}

// [z][R][C] fp32 -> [z][C][R] fp16. dst resolved in DEVICE code.
__global__ void transp_kernel(const float* __restrict__ srcR, const float* __restrict__ srcS,
                              int which, int R, int C) {
    __half* __restrict__ dst0 = which ? g_w2t : g_w1t;
    const int z = blockIdx.z;
    const float* src = (z < NEXP) ? srcR + (size_t)z * R * C : srcS + (size_t)(z - NEXP) * R * C;
    __half* d = dst0 + (size_t)z * R * C;
    __shared__ float tile[32][33];
    const int c0 = blockIdx.x * 32, r0 = blockIdx.y * 32;
    const int tx = threadIdx.x, ty = threadIdx.y;
    #pragma unroll
    for (int q = 0; q < 4; q++)
        tile[ty + 8 * q][tx] = src[(size_t)(r0 + ty + 8 * q) * C + c0 + tx];
    __syncthreads();
    #pragma unroll
    for (int q = 0; q < 4; q++)
        d[(size_t)(c0 + ty + 8 * q) * R + r0 + tx] = __float2half_rn(tile[tx][ty + 8 * q]);
}

// ---------------- fp16 mma grouped GEMM: CTA 128x128, 4 warps of 64x64 ----------------
#define BM 128
#define BN 128
#define BK 32
#define NTHR 128
#define STAGE_B 16384           // 8KB A + 8KB B; 3 stages = 48KB static

__device__ __forceinline__ uint32_t swz(int row, int q) {
    return (uint32_t)(row * 64 + ((q ^ ((row >> 1) & 3)) << 4));
}

template<int KTOT, bool G1>
__global__ __launch_bounds__(NTHR, 2) void moe_mma(
    const float* __restrict__ bias_r, const float* __restrict__ bias_s,
    float* __restrict__ out)
{
    constexpr int NC = KTOT / BK;
    const int z = blockIdx.z;

    int cnt, hbase;
    if (z < NEXP) {
        cnt = g_cnt[z];
        int b = 0;
        #pragma unroll
        for (int e = 0; e < NEXP; e++) if (e < z) b += g_cnt[e];
        hbase = b;
    } else {
        cnt = NTOK;
        hbase = 8192 + (z - NEXP) * NTOK;
    }

    const int m0 = blockIdx.x * BM;
    if (m0 >= cnt) return;
    const int n0 = blockIdx.y * BN;

    __shared__ __align__(1024) uint8_t smbuf[3 * STAGE_B];
    const uint32_t sb = smem_u32(smbuf);

    const int tid = threadIdx.x, lane = tid & 31, wid = tid >> 5;
    const int wm = (wid & 1) * 64, wn = (wid >> 1) * 64;   // 2x2 warps of 64x64

    // ---- loader plan: thread -> one A row + one B row (row tid), 4 quads each ----
    const __half* asrc;
    if (G1) {
        int tok;
        if (z < NEXP) {
            const int i0 = m0 + tid;
            tok = g_slot_tok[z][i0 < cnt ? i0 : cnt - 1];
        } else tok = m0 + tid;
        asrc = g_xh + (size_t)tok * D_MODEL;
    } else {
        asrc = g_h + (size_t)(hbase + m0 + tid) * HIDDEN;
    }
    const __half* Bt = (G1 ? g_w1t : g_w2t) + (size_t)z * D_MODEL * HIDDEN;
    const __half* bsrc = Bt + (size_t)(n0 + tid) * KTOT;

    uint32_t dA[4], dB[4];
    #pragma unroll
    for (int q = 0; q < 4; q++) {
        dA[q] = swz(tid, q);
        dB[q] = 8192u + dA[q];
    }

    // ---- fragment lane constants ----
    const int g  = lane >> 3, rin = lane & 7;
    const int gl = g & 1, gh = g >> 1;
    uint32_t aRow[4]; int aF[4];
    #pragma unroll
    for (int mt = 0; mt < 4; mt++) {
        const int r = wm + mt * 16 + gl * 8 + rin;
        aRow[mt] = (uint32_t)(r * 64);
        aF[mt]   = (r >> 1) & 3;
    }
    uint32_t bRow[4]; int bF[4];
    #pragma unroll
    for (int p = 0; p < 4; p++) {
        const int r = wn + p * 16 + gh * 8 + rin;
        bRow[p] = 8192u + (uint32_t)(r * 64);
        bF[p]   = (r >> 1) & 3;
    }

    float acc[4][8][4];
    #pragma unroll
    for (int mt = 0; mt < 4; mt++)
        #pragma unroll
        for (int nt = 0; nt < 8; nt++)
            #pragma unroll
            for (int q = 0; q < 4; q++) acc[mt][nt][q] = 0.0f;

    auto load_chunk = [&](int c, int s) {
        const uint32_t st = sb + (uint32_t)s * STAGE_B;
        const int ko = c * BK;
        #pragma unroll
        for (int q = 0; q < 4; q++) {
            cp16(st + dA[q], asrc + ko + q * 8);
            cp16(st + dB[q], bsrc + ko + q * 8);
        }
        CP_COMMIT();
    };

    load_chunk(0, 0);
    load_chunk(1, 1);

    int s = 0, s2 = 2;
    #pragma unroll 1
    for (int c = 0; c < NC; c++) {
        if (c + 1 < NC) cp_wait<1>(); else cp_wait<0>();
        __syncthreads();
        if (c + 2 < NC) load_chunk(c + 2, s2);

        const uint32_t st = sb + (uint32_t)s * STAGE_B;
        #pragma unroll
        for (int kk = 0; kk < 2; kk++) {
            uint32_t a[4][4], b[8][2];
            #pragma unroll
            for (int mt = 0; mt < 4; mt++)
                ldsm4(a[mt][0], a[mt][1], a[mt][2], a[mt][3],
                      st + aRow[mt] + (uint32_t)(((2 * kk + gh) ^ aF[mt]) << 4));
            #pragma unroll
            for (int p = 0; p < 4; p++) {
                uint32_t r0, r1, r2, r3;
                ldsm4(r0, r1, r2, r3, st + bRow[p] + (uint32_t)(((2 * kk + gl) ^ bF[p]) << 4));
                b[2 * p][0] = r0; b[2 * p][1] = r1;
                b[2 * p + 1][0] = r2; b[2 * p + 1][1] = r3;
            }
            #pragma unroll
            for (int mt = 0; mt < 4; mt++)
                #pragma unroll
                for (int nt = 0; nt < 8; nt++)
                    mma_f16(acc[mt][nt], a[mt], b[nt]);
        }
        s = (s == 2) ? 0 : s + 1;
        s2 = (s2 == 2) ? 0 : s2 + 1;
    }

    // ---------------- epilogue (C frag: rows fr(+8), cols 2*fc(+1)) ----------------
    const int fr = lane >> 2, fc = lane & 3;
    if (G1) {
        const float* bias = (z < NEXP) ? bias_r + (size_t)z * HIDDEN + n0
                                       : bias_s + (size_t)(z - NEXP) * HIDDEN + n0;
        #pragma unroll
        for (int mt = 0; mt < 4; mt++) {
            #pragma unroll
            for (int h2 = 0; h2 < 2; h2++) {
                const int mloc = wm + mt * 16 + fr + 8 * h2;
                if (m0 + mloc < cnt) {
                    __half* hrow = g_h + (size_t)(hbase + m0 + mloc) * HIDDEN + n0;
                    #pragma unroll
                    for (int nt = 0; nt < 8; nt++) {
                        const int col = wn + nt * 8 + 2 * fc;
                        const float v0 = gelu_exact(acc[mt][nt][2 * h2]     + bias[col]);
                        const float v1 = gelu_exact(acc[mt][nt][2 * h2 + 1] + bias[col + 1]);
                        *(__half2*)(hrow + col) = __floats2half2_rn(v0, v1);
                    }
                }
            }
        }
    } else {
        #pragma unroll
        for (int mt = 0; mt < 4; mt++) {
            #pragma unroll
            for (int h2 = 0; h2 < 2; h2++) {
                const int mloc = wm + mt * 16 + fr + 8 * h2;
                const int m = m0 + mloc;
                if (m < cnt) {
                    int t; float w;
                    if (z < NEXP) { t = g_slot_tok[z][m]; w = g_slot_w[z][m]; }
                    else          { t = m; w = 0.5f; }
                    float* orow = out + (size_t)t * D_MODEL + n0;
                    #pragma unroll
                    for (int nt = 0; nt < 8; nt++) {
                        const int col = wn + nt * 8 + 2 * fc;
                        atomicAdd(orow + col,     w * acc[mt][nt][2 * h2]);
                        atomicAdd(orow + col + 1, w * acc[mt][nt][2 * h2 + 1]);
                    }
                }
            }
        }
    }
}

// ---------------- launch ----------------
extern "C" void kernel_launch(void* const* d_in, const int* in_sizes, int n_in,
                              void* d_out, int out_size) {
    (void)in_sizes; (void)n_in; (void)out_size;
    const float* x   = (const float*)d_in[0];
    const float* rW  = (const float*)d_in[1];
    const float* rb  = (const float*)d_in[2];
    const float* W1  = (const float*)d_in[3];
    const float* b1  = (const float*)d_in[4];
    const float* W2  = (const float*)d_in[5];
    const float* b2  = (const float*)d_in[6];
    const float* sW1 = (const float*)d_in[7];
    const float* sb1 = (const float*)d_in[8];
    const float* sW2 = (const float*)d_in[9];
    const float* sb2 = (const float*)d_in[10];
    float* out = (float*)d_out;

    // moe_mma<G1> kept as the 4th launch (ncu capture slot)
    conv_x_kernel<<<(NTOK * D_MODEL) / 1024, 256>>>(x);                   // 1
    transp_kernel<<<dim3(HIDDEN / 32, D_MODEL / 32, NZ), dim3(32, 8)>>>(  // 2
        W1, sW1, 0, D_MODEL, HIDDEN);
    router_kernel<<<NTOK, 128>>>(x, rW, rb);                              // 3
    moe_mma<D_MODEL, true><<<dim3(CAP / BM, HIDDEN / BN, NZ), NTHR>>>(    // 4
        b1, sb1, nullptr);
    transp_kernel<<<dim3(D_MODEL / 32, HIDDEN / 32, NZ), dim3(32, 8)>>>(  // 5
        W2, sW2, 1, HIDDEN, D_MODEL);
    init_out_kernel<<<(NTOK * D_MODEL) / 256, 256>>>(out, b2, sb2);       // 6
    moe_mma<HIDDEN, false><<<dim3(CAP / BM, D_MODEL / BN, NZ), NTHR>>>(   // 7
        nullptr, nullptr, out);
}

// round 14
// speedup vs baseline: 1.5433x; 1.5433x over previous
#include <cuda_runtime.h>
#include <cuda_fp16.h>
#include <cstdint>
#include <math.h>

#define D_MODEL 1024
#define HIDDEN  4096
#define NEXP    8
#define NSH     2
#define NTOK    4096
#define CAP     4096
#define NZ      (NEXP + NSH)
#define NSLOT   16384

// ---------------- device scratch (static; zero runtime allocation) ----------------
__device__ int   g_cnt[NEXP];
__device__ int   g_ctr[2];                 // persistent-GEMM work counters
__device__ int   g_slot_tok[NEXP][CAP];
__device__ float g_slot_w[NEXP][CAP];
__device__ int   g_tok_e[NTOK][2];
__device__ float g_tok_w[NTOK][2];

__device__ __align__(16) __half g_xh[(size_t)NTOK * D_MODEL];            // x fp16
__device__ __align__(16) __half g_w1t[(size_t)NZ * HIDDEN * D_MODEL];    // W1^T fp16 [z][H][D]
__device__ __align__(16) __half g_w2t[(size_t)NZ * D_MODEL * HIDDEN];    // W2^T fp16 [z][D][H]
__device__ __align__(16) __half g_h[(size_t)NSLOT * HIDDEN];             // hidden acts fp16

__device__ __forceinline__ float gelu_exact(float v) {
    return 0.5f * v * (1.0f + erff(v * 0.70710678118654752440f));
}

// ---------------- PTX helpers ----------------
__device__ __forceinline__ uint32_t smem_u32(const void* p) {
    uint32_t a;
    asm("{ .reg .u64 t; cvta.to.shared.u64 t, %1; cvt.u32.u64 %0, t; }" : "=r"(a) : "l"(p));
    return a;
}
__device__ __forceinline__ void cp16(uint32_t dst, const void* src) {
    asm volatile("cp.async.cg.shared.global [%0], [%1], 16;\n" :: "r"(dst), "l"(src) : "memory");
}
#define CP_COMMIT() asm volatile("cp.async.commit_group;\n" ::: "memory")
template<int N> __device__ __forceinline__ void cp_wait() {
    asm volatile("cp.async.wait_group %0;\n" :: "n"(N) : "memory");
}
__device__ __forceinline__ void ldsm4(uint32_t& r0, uint32_t& r1, uint32_t& r2, uint32_t& r3,
                                      uint32_t addr) {
    asm volatile("ldmatrix.sync.aligned.m8n8.x4.shared.b16 {%0,%1,%2,%3}, [%4];"
                 : "=r"(r0), "=r"(r1), "=r"(r2), "=r"(r3) : "r"(addr));
}
__device__ __forceinline__ void mma_f16(float* d, const uint32_t* a, const uint32_t* b) {
    asm volatile(
        "mma.sync.aligned.m16n8k16.row.col.f32.f16.f16.f32 "
        "{%0,%1,%2,%3}, {%4,%5,%6,%7}, {%8,%9}, {%0,%1,%2,%3};"
        : "+f"(d[0]), "+f"(d[1]), "+f"(d[2]), "+f"(d[3])
        : "r"(a[0]), "r"(a[1]), "r"(a[2]), "r"(a[3]), "r"(b[0]), "r"(b[1]));
}

// ---------------- small kernels ----------------
__global__ void zero_kernel() {
    if (threadIdx.x < NEXP) g_cnt[threadIdx.x] = 0;
    if (threadIdx.x < 2)    g_ctr[threadIdx.x] = 0;
}

// router; also converts x -> fp16 (fused, reuses the loaded values)
__global__ void router_kernel(const float* __restrict__ x,
                              const float* __restrict__ rW,
                              const float* __restrict__ rb) {
    const int t = blockIdx.x, tid = threadIdx.x;
    __shared__ float sg[128][NEXP];
    float acc[NEXP];
    #pragma unroll
    for (int e = 0; e < NEXP; e++) acc[e] = 0.0f;
    const float* xr = x + (size_t)t * D_MODEL;
    __half* xh = g_xh + (size_t)t * D_MODEL;
    for (int d = tid; d < D_MODEL; d += 128) {
        const float xv = xr[d];
        xh[d] = __float2half_rn(xv);
        const float* r = rW + (size_t)d * NEXP;
        #pragma unroll
        for (int e = 0; e < NEXP; e++) acc[e] += xv * r[e];
    }
    #pragma unroll
    for (int e = 0; e < NEXP; e++) sg[tid][e] = acc[e];
    __syncthreads();
    if (tid < NEXP) {
        float s = rb[tid];
        for (int i = 0; i < 128; i++) s += sg[i][tid];
        sg[0][tid] = s;
    }
    __syncthreads();
    if (tid == 0) {
        float g[NEXP];
        #pragma unroll
        for (int e = 0; e < NEXP; e++) g[e] = sg[0][e];
        int e0 = 0;
        #pragma unroll
        for (int e = 1; e < NEXP; e++) if (g[e] > g[e0]) e0 = e;
        int e1 = (e0 == 0) ? 1 : 0;
        #pragma unroll
        for (int e = 0; e < NEXP; e++) if (e != e0 && g[e] > g[e1]) e1 = e;
        const float p1 = expf(g[e1] - g[e0]);
        const float inv = 1.0f / (1.0f + p1);
        const float w0 = inv, w1 = p1 * inv;
        g_tok_e[t][0] = e0; g_tok_e[t][1] = e1;
        g_tok_w[t][0] = w0; g_tok_w[t][1] = w1;
        int p = atomicAdd(&g_cnt[e0], 1);
        g_slot_tok[e0][p] = t; g_slot_w[e0][p] = w0;
        p = atomicAdd(&g_cnt[e1], 1);
        g_slot_tok[e1][p] = t; g_slot_w[e1][p] = w1;
    }
}

__global__ void init_out_kernel(float* __restrict__ out,
                                const float* __restrict__ b2,
                                const float* __restrict__ sb2) {
    const int idx = blockIdx.x * 256 + threadIdx.x;
    if (idx >= NTOK * D_MODEL) return;
    const int t = idx >> 10, d = idx & 1023;
    float v = 0.5f * (sb2[d] + sb2[D_MODEL + d]);
    v += g_tok_w[t][0] * b2[(size_t)g_tok_e[t][0] * D_MODEL + d];
    v += g_tok_w[t][1] * b2[(size_t)g_tok_e[t][1] * D_MODEL + d];
    out[idx] = v;
}

// [z][R][C] fp32 -> [z][C][R] fp16. dst resolved in DEVICE code.
__global__ void transp_kernel(const float* __restrict__ srcR, const float* __restrict__ srcS,
                              int which, int R, int C) {
    __half* __restrict__ dst0 = which ? g_w2t : g_w1t;
    const int z = blockIdx.z;
    const float* src = (z < NEXP) ? srcR + (size_t)z * R * C : srcS + (size_t)(z - NEXP) * R * C;
    __half* d = dst0 + (size_t)z * R * C;
    __shared__ float tile[32][33];
    const int c0 = blockIdx.x * 32, r0 = blockIdx.y * 32;
    const int tx = threadIdx.x, ty = threadIdx.y;
    #pragma unroll
    for (int q = 0; q < 4; q++)
        tile[ty + 8 * q][tx] = src[(size_t)(r0 + ty + 8 * q) * C + c0 + tx];
    __syncthreads();
    #pragma unroll
    for (int q = 0; q < 4; q++)
        d[(size_t)(c0 + ty + 8 * q) * R + r0 + tx] = __float2half_rn(tile[tx][ty + 8 * q]);
}

// ---------------- persistent fp16 mma grouped GEMM (R11 core inside tile loop) ----------------
#define BM 128
#define BN 128
#define BK 32
#define STAGE_B 16384           // 8KB A + 8KB B; 3 stages = 48KB static
#define NPERS 304               // 2 CTAs per SM on 152 SMs

__device__ __forceinline__ uint32_t swz(int row, int q) {
    return (uint32_t)(row * 64 + ((q ^ ((row >> 1) & 3)) << 4));
}

template<int KTOT, bool G1>
__global__ __launch_bounds__(256, 2) void moe_mma(
    const float* __restrict__ bias_r, const float* __restrict__ bias_s,
    float* __restrict__ out)
{
    constexpr int NC = KTOT / BK;
    constexpr int TX = CAP / BM;                       // 32
    constexpr int TY = (G1 ? HIDDEN : D_MODEL) / BN;   // 32 / 8
    constexpr int TOT = TX * TY * NZ;

    __shared__ __align__(1024) uint8_t smbuf[3 * STAGE_B];
    __shared__ int s_t;
    const uint32_t sb = smem_u32(smbuf);

    const int tid = threadIdx.x, lane = tid & 31, wid = tid >> 5;
    const int wm = (wid & 1) * 64, wn = (wid >> 1) * 32;

    // ---- tile-independent constants ----
    const int lr = tid >> 2, lq = tid & 3;
    const uint32_t dA0 = swz(lr, lq), dA1 = swz(lr + 64, lq);
    const uint32_t dB0 = 8192u + dA0, dB1 = 8192u + dA1;

    const int g  = lane >> 3, rin = lane & 7;
    const int gl = g & 1, gh = g >> 1;
    uint32_t aRow[4]; int aF[4];
    #pragma unroll
    for (int mt = 0; mt < 4; mt++) {
        const int r = wm + mt * 16 + gl * 8 + rin;
        aRow[mt] = (uint32_t)(r * 64);
        aF[mt]   = (r >> 1) & 3;
    }
    uint32_t bRow[2]; int bF[2];
    #pragma unroll
    for (int p = 0; p < 2; p++) {
        const int r = wn + p * 16 + gh * 8 + rin;
        bRow[p] = 8192u + (uint32_t)(r * 64);
        bF[p]   = (r >> 1) & 3;
    }
    const int fr = lane >> 2, fc = lane & 3;

    // ---- persistent tile loop ----
    while (true) {
        __syncthreads();
        if (tid == 0) s_t = atomicAdd(&g_ctr[G1 ? 0 : 1], 1);
        __syncthreads();
        const int twork = s_t;
        if (twork >= TOT) break;

        const int xb = twork % TX;
        const int rest = twork / TX;
        const int yb = rest % TY;
        const int z  = rest / TY;

        int cnt, hbase;
        if (z < NEXP) {
            cnt = g_cnt[z];
            int b = 0;
            #pragma unroll
            for (int e = 0; e < NEXP; e++) if (e < z) b += g_cnt[e];
            hbase = b;
        } else {
            cnt = NTOK;
            hbase = 8192 + (z - NEXP) * NTOK;
        }
        const int m0 = xb * BM;
        if (m0 >= cnt) continue;
        const int n0 = yb * BN;

        // ---- per-tile loader sources ----
        const __half* asrc0;
        const __half* asrc1;
        if (G1) {
            int t0, t1;
            if (z < NEXP) {
                const int i0 = m0 + lr, i1 = m0 + lr + 64;
                t0 = g_slot_tok[z][i0 < cnt ? i0 : cnt - 1];
                t1 = g_slot_tok[z][i1 < cnt ? i1 : cnt - 1];
            } else { t0 = m0 + lr; t1 = m0 + lr + 64; }
            asrc0 = g_xh + (size_t)t0 * D_MODEL + lq * 8;
            asrc1 = g_xh + (size_t)t1 * D_MODEL + lq * 8;
        } else {
            asrc0 = g_h + (size_t)(hbase + m0 + lr) * HIDDEN + lq * 8;
            asrc1 = g_h + (size_t)(hbase + m0 + lr + 64) * HIDDEN + lq * 8;
        }
        const __half* Bt = (G1 ? g_w1t : g_w2t) + (size_t)z * D_MODEL * HIDDEN;
        const __half* bsrc0 = Bt + (size_t)(n0 + lr) * KTOT + lq * 8;
        const __half* bsrc1 = Bt + (size_t)(n0 + lr + 64) * KTOT + lq * 8;

        float acc[4][4][4];
        #pragma unroll
        for (int mt = 0; mt < 4; mt++)
            #pragma unroll
            for (int nt = 0; nt < 4; nt++)
                #pragma unroll
                for (int q = 0; q < 4; q++) acc[mt][nt][q] = 0.0f;

        auto load_chunk = [&](int c, int s) {
            const uint32_t st = sb + (uint32_t)s * STAGE_B;
            const int ko = c * BK;
            cp16(st + dA0, asrc0 + ko);
            cp16(st + dA1, asrc1 + ko);
            cp16(st + dB0, bsrc0 + ko);
            cp16(st + dB1, bsrc1 + ko);
            CP_COMMIT();
        };

        load_chunk(0, 0);
        load_chunk(1, 1);

        int s = 0, s2 = 2;
        #pragma unroll 1
        for (int c = 0; c < NC; c++) {
            if (c + 1 < NC) cp_wait<1>(); else cp_wait<0>();
            __syncthreads();
            if (c + 2 < NC) load_chunk(c + 2, s2);

            const uint32_t st = sb + (uint32_t)s * STAGE_B;
            #pragma unroll
            for (int kk = 0; kk < 2; kk++) {
                uint32_t a[4][4], b[4][2];
                #pragma unroll
                for (int mt = 0; mt < 4; mt++)
                    ldsm4(a[mt][0], a[mt][1], a[mt][2], a[mt][3],
                          st + aRow[mt] + (uint32_t)(((2 * kk + gh) ^ aF[mt]) << 4));
                {
                    uint32_t r0, r1, r2, r3;
                    ldsm4(r0, r1, r2, r3, st + bRow[0] + (uint32_t)(((2 * kk + gl) ^ bF[0]) << 4));
                    b[0][0] = r0; b[0][1] = r1; b[1][0] = r2; b[1][1] = r3;
                    ldsm4(r0, r1, r2, r3, st + bRow[1] + (uint32_t)(((2 * kk + gl) ^ bF[1]) << 4));
                    b[2][0] = r0; b[2][1] = r1; b[3][0] = r2; b[3][1] = r3;
                }
                #pragma unroll
                for (int mt = 0; mt < 4; mt++)
                    #pragma unroll
                    for (int nt = 0; nt < 4; nt++)
                        mma_f16(acc[mt][nt], a[mt], b[nt]);
            }
            s = (s == 2) ? 0 : s + 1;
            s2 = (s2 == 2) ? 0 : s2 + 1;
        }

        // ---- epilogue ----
        if (G1) {
            const float* bias = (z < NEXP) ? bias_r + (size_t)z * HIDDEN + n0
                                           : bias_s + (size_t)(z - NEXP) * HIDDEN + n0;
            #pragma unroll
            for (int mt = 0; mt < 4; mt++) {
                #pragma unroll
                for (int h2 = 0; h2 < 2; h2++) {
                    const int mloc = wm + mt * 16 + fr + 8 * h2;
                    if (m0 + mloc < cnt) {
                        __half* hrow = g_h + (size_t)(hbase + m0 + mloc) * HIDDEN + n0;
                        #pragma unroll
                        for (int nt = 0; nt < 4; nt++) {
                            const int col = wn + nt * 8 + 2 * fc;
                            const float v0 = gelu_exact(acc[mt][nt][2 * h2]     + bias[col]);
                            const float v1 = gelu_exact(acc[mt][nt][2 * h2 + 1] + bias[col + 1]);
                            *(__half2*)(hrow + col) = __floats2half2_rn(v0, v1);
                        }
                    }
                }
            }
        } else {
            #pragma unroll
            for (int mt = 0; mt < 4; mt++) {
                #pragma unroll
                for (int h2 = 0; h2 < 2; h2++) {
                    const int mloc = wm + mt * 16 + fr + 8 * h2;
                    const int m = m0 + mloc;
                    if (m < cnt) {
                        int t; float w;
                        if (z < NEXP) { t = g_slot_tok[z][m]; w = g_slot_w[z][m]; }
                        else          { t = m; w = 0.5f; }
                        float* orow = out + (size_t)t * D_MODEL + n0;
                        #pragma unroll
                        for (int nt = 0; nt < 4; nt++) {
                            const int col = wn + nt * 8 + 2 * fc;
                            atomicAdd(orow + col,     w * acc[mt][nt][2 * h2]);
                            atomicAdd(orow + col + 1, w * acc[mt][nt][2 * h2 + 1]);
                        }
                    }
                }
            }
        }
    }
}

// ---------------- launch ----------------
extern "C" void kernel_launch(void* const* d_in, const int* in_sizes, int n_in,
                              void* d_out, int out_size) {
    (void)in_sizes; (void)n_in; (void)out_size;
    const float* x   = (const float*)d_in[0];
    const float* rW  = (const float*)d_in[1];
    const float* rb  = (const float*)d_in[2];
    const float* W1  = (const float*)d_in[3];
    const float* b1  = (const float*)d_in[4];
    const float* W2  = (const float*)d_in[5];
    const float* b2  = (const float*)d_in[6];
    const float* sW1 = (const float*)d_in[7];
    const float* sb1 = (const float*)d_in[8];
    const float* sW2 = (const float*)d_in[9];
    const float* sb2 = (const float*)d_in[10];
    float* out = (float*)d_out;

    // moe_mma<G1> kept as the 4th launch (ncu capture slot)
    zero_kernel<<<1, 32>>>();                                             // 1
    router_kernel<<<NTOK, 128>>>(x, rW, rb);                              // 2 (also x->fp16)
    transp_kernel<<<dim3(HIDDEN / 32, D_MODEL / 32, NZ), dim3(32, 8)>>>(  // 3
        W1, sW1, 0, D_MODEL, HIDDEN);
    moe_mma<D_MODEL, true><<<NPERS, 256>>>(b1, sb1, nullptr);             // 4 (persistent)
    transp_kernel<<<dim3(D_MODEL / 32, HIDDEN / 32, NZ), dim3(32, 8)>>>(  // 5
        W2, sW2, 1, HIDDEN, D_MODEL);
    init_out_kernel<<<(NTOK * D_MODEL) / 256, 256>>>(out, b2, sb2);       // 6
    moe_mma<HIDDEN, false><<<NPERS, 256>>>(nullptr, nullptr, out);        // 7 (persistent)
}

// round 15
// speedup vs baseline: 1.5438x; 1.0003x over previous
#include <cuda_runtime.h>
#include <cuda_fp16.h>
#include <cstdint>
#include <math.h>

#define D_MODEL 1024
#define HIDDEN  4096
#define NEXP    8
#define NSH     2
#define NTOK    4096
#define CAP     4096
#define NZ      (NEXP + NSH)
#define NSLOT   16384

// ---------------- device scratch (static; zero runtime allocation) ----------------
__device__ int   g_cnt[NEXP];
__device__ int   g_ctr[2];                 // persistent-GEMM work counters
__device__ int   g_slot_tok[NEXP][CAP];
__device__ float g_slot_w[NEXP][CAP];
__device__ int   g_tok_e[NTOK][2];
__device__ float g_tok_w[NTOK][2];

__device__ __align__(16) __half g_xh[(size_t)NTOK * D_MODEL];            // x fp16
__device__ __align__(16) __half g_w1t[(size_t)NZ * HIDDEN * D_MODEL];    // W1^T fp16 [z][H][D]
__device__ __align__(16) __half g_w2t[(size_t)NZ * D_MODEL * HIDDEN];    // W2^T fp16 [z][D][H]
__device__ __align__(16) __half g_h[(size_t)NSLOT * HIDDEN];             // hidden acts fp16

__device__ __forceinline__ float gelu_exact(float v) {
    return 0.5f * v * (1.0f + erff(v * 0.70710678118654752440f));
}

// ---------------- PTX helpers ----------------
__device__ __forceinline__ uint32_t smem_u32(const void* p) {
    uint32_t a;
    asm("{ .reg .u64 t; cvta.to.shared.u64 t, %1; cvt.u32.u64 %0, t; }" : "=r"(a) : "l"(p));
    return a;
}
__device__ __forceinline__ void cp16(uint32_t dst, const void* src) {
    asm volatile("cp.async.cg.shared.global [%0], [%1], 16;\n" :: "r"(dst), "l"(src) : "memory");
}
#define CP_COMMIT() asm volatile("cp.async.commit_group;\n" ::: "memory")
template<int N> __device__ __forceinline__ void cp_wait() {
    asm volatile("cp.async.wait_group %0;\n" :: "n"(N) : "memory");
}
__device__ __forceinline__ void ldsm4(uint32_t& r0, uint32_t& r1, uint32_t& r2, uint32_t& r3,
                                      uint32_t addr) {
    asm volatile("ldmatrix.sync.aligned.m8n8.x4.shared.b16 {%0,%1,%2,%3}, [%4];"
                 : "=r"(r0), "=r"(r1), "=r"(r2), "=r"(r3) : "r"(addr));
}
__device__ __forceinline__ void mma_f16(float* d, const uint32_t* a, const uint32_t* b) {
    asm volatile(
        "mma.sync.aligned.m16n8k16.row.col.f32.f16.f16.f32 "
        "{%0,%1,%2,%3}, {%4,%5,%6,%7}, {%8,%9}, {%0,%1,%2,%3};"
        : "+f"(d[0]), "+f"(d[1]), "+f"(d[2]), "+f"(d[3])
        : "r"(a[0]), "r"(a[1]), "r"(a[2]), "r"(a[3]), "r"(b[0]), "r"(b[1]));
}

// ---------------- small kernels ----------------
__global__ void zero_kernel() {
    if (threadIdx.x < NEXP) g_cnt[threadIdx.x] = 0;
    if (threadIdx.x < 2)    g_ctr[threadIdx.x] = 0;
}

// router; also converts x -> fp16 (fused, reuses the loaded values)
__global__ void router_kernel(const float* __restrict__ x,
                              const float* __restrict__ rW,
                              const float* __restrict__ rb) {
    const int t = blockIdx.x, tid = threadIdx.x;
    __shared__ float sg[128][NEXP];
    float acc[NEXP];
    #pragma unroll
    for (int e = 0; e < NEXP; e++) acc[e] = 0.0f;
    const float* xr = x + (size_t)t * D_MODEL;
    __half* xh = g_xh + (size_t)t * D_MODEL;
    for (int d = tid; d < D_MODEL; d += 128) {
        const float xv = xr[d];
        xh[d] = __float2half_rn(xv);
        const float* r = rW + (size_t)d * NEXP;
        #pragma unroll
        for (int e = 0; e < NEXP; e++) acc[e] += xv * r[e];
    }
    #pragma unroll
    for (int e = 0; e < NEXP; e++) sg[tid][e] = acc[e];
    __syncthreads();
    if (tid < NEXP) {
        float s = rb[tid];
        for (int i = 0; i < 128; i++) s += sg[i][tid];
        sg[0][tid] = s;
    }
    __syncthreads();
    if (tid == 0) {
        float g[NEXP];
        #pragma unroll
        for (int e = 0; e < NEXP; e++) g[e] = sg[0][e];
        int e0 = 0;
        #pragma unroll
        for (int e = 1; e < NEXP; e++) if (g[e] > g[e0]) e0 = e;
        int e1 = (e0 == 0) ? 1 : 0;
        #pragma unroll
        for (int e = 0; e < NEXP; e++) if (e != e0 && g[e] > g[e1]) e1 = e;
        const float p1 = expf(g[e1] - g[e0]);
        const float inv = 1.0f / (1.0f + p1);
        const float w0 = inv, w1 = p1 * inv;
        g_tok_e[t][0] = e0; g_tok_e[t][1] = e1;
        g_tok_w[t][0] = w0; g_tok_w[t][1] = w1;
        int p = atomicAdd(&g_cnt[e0], 1);
        g_slot_tok[e0][p] = t; g_slot_w[e0][p] = w0;
        p = atomicAdd(&g_cnt[e1], 1);
        g_slot_tok[e1][p] = t; g_slot_w[e1][p] = w1;
    }
}

__global__ void init_out_kernel(float* __restrict__ out,
                                const float* __restrict__ b2,
                                const float* __restrict__ sb2) {
    const int idx = blockIdx.x * 256 + threadIdx.x;
    if (idx >= NTOK * D_MODEL) return;
    const int t = idx >> 10, d = idx & 1023;
    float v = 0.5f * (sb2[d] + sb2[D_MODEL + d]);
    v += g_tok_w[t][0] * b2[(size_t)g_tok_e[t][0] * D_MODEL + d];
    v += g_tok_w[t][1] * b2[(size_t)g_tok_e[t][1] * D_MODEL + d];
    out[idx] = v;
}

// [z][R][C] fp32 -> [z][C][R] fp16. dst resolved in DEVICE code.
__global__ void transp_kernel(const float* __restrict__ srcR, const float* __restrict__ srcS,
                              int which, int R, int C) {
    __half* __restrict__ dst0 = which ? g_w2t : g_w1t;
    const int z = blockIdx.z;
    const float* src = (z < NEXP) ? srcR + (size_t)z * R * C : srcS + (size_t)(z - NEXP) * R * C;
    __half* d = dst0 + (size_t)z * R * C;
    __shared__ float tile[32][33];
    const int c0 = blockIdx.x * 32, r0 = blockIdx.y * 32;
    const int tx = threadIdx.x, ty = threadIdx.y;
    #pragma unroll
    for (int q = 0; q < 4; q++)
        tile[ty + 8 * q][tx] = src[(size_t)(r0 + ty + 8 * q) * C + c0 + tx];
    __syncthreads();
    #pragma unroll
    for (int q = 0; q < 4; q++)
        d[(size_t)(c0 + ty + 8 * q) * R + r0 + tx] = __float2half_rn(tile[tx][ty + 8 * q]);
}

// ---------------- persistent fp16 mma grouped GEMM (R11 core inside tile loop) ----------------
#define BM 128
#define BN 128
#define BK 32
#define STAGE_B 16384           // 8KB A + 8KB B; 3 stages = 48KB static
#define NPERS 304               // 2 CTAs per SM on 152 SMs

__device__ __forceinline__ uint32_t swz(int row, int q) {
    return (uint32_t)(row * 64 + ((q ^ ((row >> 1) & 3)) << 4));
}

template<int KTOT, bool G1>
__global__ __launch_bounds__(256, 2) void moe_mma(
    const float* __restrict__ bias_r, const float* __restrict__ bias_s,
    float* __restrict__ out)
{
    constexpr int NC = KTOT / BK;
    constexpr int TX = CAP / BM;                       // 32
    constexpr int TY = (G1 ? HIDDEN : D_MODEL) / BN;   // 32 / 8
    constexpr int TOT = TX * TY * NZ;

    __shared__ __align__(1024) uint8_t smbuf[3 * STAGE_B];
    __shared__ int s_t;
    const uint32_t sb = smem_u32(smbuf);

    const int tid = threadIdx.x, lane = tid & 31, wid = tid >> 5;
    const int wm = (wid & 1) * 64, wn = (wid >> 1) * 32;

    // ---- tile-independent constants ----
    const int lr = tid >> 2, lq = tid & 3;
    const uint32_t dA0 = swz(lr, lq), dA1 = swz(lr + 64, lq);
    const uint32_t dB0 = 8192u + dA0, dB1 = 8192u + dA1;

    const int g  = lane >> 3, rin = lane & 7;
    const int gl = g & 1, gh = g >> 1;
    uint32_t aRow[4]; int aF[4];
    #pragma unroll
    for (int mt = 0; mt < 4; mt++) {
        const int r = wm + mt * 16 + gl * 8 + rin;
        aRow[mt] = (uint32_t)(r * 64);
        aF[mt]   = (r >> 1) & 3;
    }
    uint32_t bRow[2]; int bF[2];
    #pragma unroll
    for (int p = 0; p < 2; p++) {
        const int r = wn + p * 16 + gh * 8 + rin;
        bRow[p] = 8192u + (uint32_t)(r * 64);
        bF[p]   = (r >> 1) & 3;
    }
    const int fr = lane >> 2, fc = lane & 3;

    // ---- persistent tile loop ----
    while (true) {
        __syncthreads();
        if (tid == 0) s_t = atomicAdd(&g_ctr[G1 ? 0 : 1], 1);
        __syncthreads();
        const int twork = s_t;
        if (twork >= TOT) break;

        const int xb = twork % TX;
        const int rest = twork / TX;
        const int yb = rest % TY;
        const int z  = rest / TY;

        int cnt, hbase;
        if (z < NEXP) {
            cnt = g_cnt[z];
            int b = 0;
            #pragma unroll
            for (int e = 0; e < NEXP; e++) if (e < z) b += g_cnt[e];
            hbase = b;
        } else {
            cnt = NTOK;
            hbase = 8192 + (z - NEXP) * NTOK;
        }
        const int m0 = xb * BM;
        if (m0 >= cnt) continue;
        const int n0 = yb * BN;

        // ---- per-tile loader sources ----
        const __half* asrc0;
        const __half* asrc1;
        if (G1) {
            int t0, t1;
            if (z < NEXP) {
                const int i0 = m0 + lr, i1 = m0 + lr + 64;
                t0 = g_slot_tok[z][i0 < cnt ? i0 : cnt - 1];
                t1 = g_slot_tok[z][i1 < cnt ? i1 : cnt - 1];
            } else { t0 = m0 + lr; t1 = m0 + lr + 64; }
            asrc0 = g_xh + (size_t)t0 * D_MODEL + lq * 8;
            asrc1 = g_xh + (size_t)t1 * D_MODEL + lq * 8;
        } else {
            asrc0 = g_h + (size_t)(hbase + m0 + lr) * HIDDEN + lq * 8;
            asrc1 = g_h + (size_t)(hbase + m0 + lr + 64) * HIDDEN + lq * 8;
        }
        const __half* Bt = (G1 ? g_w1t : g_w2t) + (size_t)z * D_MODEL * HIDDEN;
        const __half* bsrc0 = Bt + (size_t)(n0 + lr) * KTOT + lq * 8;
        const __half* bsrc1 = Bt + (size_t)(n0 + lr + 64) * KTOT + lq * 8;

        float acc[4][4][4];
        #pragma unroll
        for (int mt = 0; mt < 4; mt++)
            #pragma unroll
            for (int nt = 0; nt < 4; nt++)
                #pragma unroll
                for (int q = 0; q < 4; q++) acc[mt][nt][q] = 0.0f;

        auto load_chunk = [&](int c, int s) {
            const uint32_t st = sb + (uint32_t)s * STAGE_B;
            const int ko = c * BK;
            cp16(st + dA0, asrc0 + ko);
            cp16(st + dA1, asrc1 + ko);
            cp16(st + dB0, bsrc0 + ko);
            cp16(st + dB1, bsrc1 + ko);
            CP_COMMIT();
        };

        load_chunk(0, 0);
        load_chunk(1, 1);

        int s = 0, s2 = 2;
        #pragma unroll 1
        for (int c = 0; c < NC; c++) {
            if (c + 1 < NC) cp_wait<1>(); else cp_wait<0>();
            __syncthreads();
            if (c + 2 < NC) load_chunk(c + 2, s2);

            const uint32_t st = sb + (uint32_t)s * STAGE_B;
            #pragma unroll
            for (int kk = 0; kk < 2; kk++) {
                uint32_t a[4][4], b[4][2];
                #pragma unroll
                for (int mt = 0; mt < 4; mt++)
                    ldsm4(a[mt][0], a[mt][1], a[mt][2], a[mt][3],
                          st + aRow[mt] + (uint32_t)(((2 * kk + gh) ^ aF[mt]) << 4));
                {
                    uint32_t r0, r1, r2, r3;
                    ldsm4(r0, r1, r2, r3, st + bRow[0] + (uint32_t)(((2 * kk + gl) ^ bF[0]) << 4));
                    b[0][0] = r0; b[0][1] = r1; b[1][0] = r2; b[1][1] = r3;
                    ldsm4(r0, r1, r2, r3, st + bRow[1] + (uint32_t)(((2 * kk + gl) ^ bF[1]) << 4));
                    b[2][0] = r0; b[2][1] = r1; b[3][0] = r2; b[3][1] = r3;
                }
                #pragma unroll
                for (int mt = 0; mt < 4; mt++)
                    #pragma unroll
                    for (int nt = 0; nt < 4; nt++)
                        mma_f16(acc[mt][nt], a[mt], b[nt]);
            }
            s = (s == 2) ? 0 : s + 1;
            s2 = (s2 == 2) ? 0 : s2 + 1;
        }

        // ---- epilogue ----
        if (G1) {
            const float* bias = (z < NEXP) ? bias_r + (size_t)z * HIDDEN + n0
                                           : bias_s + (size_t)(z - NEXP) * HIDDEN + n0;
            #pragma unroll
            for (int mt = 0; mt < 4; mt++) {
                #pragma unroll
                for (int h2 = 0; h2 < 2; h2++) {
                    const int mloc = wm + mt * 16 + fr + 8 * h2;
                    if (m0 + mloc < cnt) {
                        __half* hrow = g_h + (size_t)(hbase + m0 + mloc) * HIDDEN + n0;
                        #pragma unroll
                        for (int nt = 0; nt < 4; nt++) {
                            const int col = wn + nt * 8 + 2 * fc;
                            const float v0 = gelu_exact(acc[mt][nt][2 * h2]     + bias[col]);
                            const float v1 = gelu_exact(acc[mt][nt][2 * h2 + 1] + bias[col + 1]);
                            *(__half2*)(hrow + col) = __floats2half2_rn(v0, v1);
                        }
                    }
                }
            }
        } else {
            #pragma unroll
            for (int mt = 0; mt < 4; mt++) {
                #pragma unroll
                for (int h2 = 0; h2 < 2; h2++) {
                    const int mloc = wm + mt * 16 + fr + 8 * h2;
                    const int m = m0 + mloc;
                    if (m < cnt) {
                        int t; float w;
                        if (z < NEXP) { t = g_slot_tok[z][m]; w = g_slot_w[z][m]; }
                        else          { t = m; w = 0.5f; }
                        float* orow = out + (size_t)t * D_MODEL + n0;
                        #pragma unroll
                        for (int nt = 0; nt < 4; nt++) {
                            const int col = wn + nt * 8 + 2 * fc;
                            atomicAdd(orow + col,     w * acc[mt][nt][2 * h2]);
                            atomicAdd(orow + col + 1, w * acc[mt][nt][2 * h2 + 1]);
                        }
                    }
                }
            }
        }
    }
}

// ---------------- launch ----------------
extern "C" void kernel_launch(void* const* d_in, const int* in_sizes, int n_in,
                              void* d_out, int out_size) {
    (void)in_sizes; (void)n_in; (void)out_size;
    const float* x   = (const float*)d_in[0];
    const float* rW  = (const float*)d_in[1];
    const float* rb  = (const float*)d_in[2];
    const float* W1  = (const float*)d_in[3];
    const float* b1  = (const float*)d_in[4];
    const float* W2  = (const float*)d_in[5];
    const float* b2  = (const float*)d_in[6];
    const float* sW1 = (const float*)d_in[7];
    const float* sb1 = (const float*)d_in[8];
    const float* sW2 = (const float*)d_in[9];
    const float* sb2 = (const float*)d_in[10];
    float* out = (float*)d_out;

    // moe_mma<G1> kept as the 4th launch (ncu capture slot)
    zero_kernel<<<1, 32>>>();                                             // 1
    router_kernel<<<NTOK, 128>>>(x, rW, rb);                              // 2 (also x->fp16)
    transp_kernel<<<dim3(HIDDEN / 32, D_MODEL / 32, NZ), dim3(32, 8)>>>(  // 3
        W1, sW1, 0, D_MODEL, HIDDEN);
    moe_mma<D_MODEL, true><<<NPERS, 256>>>(b1, sb1, nullptr);             // 4 (persistent)
    transp_kernel<<<dim3(D_MODEL / 32, HIDDEN / 32, NZ), dim3(32, 8)>>>(  // 5
        W2, sW2, 1, HIDDEN, D_MODEL);
    init_out_kernel<<<(NTOK * D_MODEL) / 256, 256>>>(out, b2, sb2);       // 6
    moe_mma<HIDDEN, false><<<NPERS, 256>>>(nullptr, nullptr, out);        // 7 (persistent)
}

// round 16
// speedup vs baseline: 1.5924x; 1.0315x over previous
#include <cuda_runtime.h>
#include <cuda_fp16.h>
#include <cstdint>
#include <math.h>

#define D_MODEL 1024
#define HIDDEN  4096
#define NEXP    8
#define NSH     2
#define NTOK    4096
#define CAP     4096
#define NZ      (NEXP + NSH)
#define NSLOT   16384

// ---------------- device scratch (static; zero runtime allocation) ----------------
__device__ int   g_cnt[NEXP];
__device__ int   g_slot_tok[NEXP][CAP];
__device__ float g_slot_w[NEXP][CAP];
__device__ int   g_tok_e[NTOK][2];
__device__ float g_tok_w[NTOK][2];

__device__ __align__(16) __half g_xh[(size_t)NTOK * D_MODEL];            // x fp16
__device__ __align__(16) __half g_w1t[(size_t)NZ * HIDDEN * D_MODEL];    // W1^T fp16 [z][H][D]
__device__ __align__(16) __half g_w2t[(size_t)NZ * D_MODEL * HIDDEN];    // W2^T fp16 [z][D][H]
__device__ __align__(16) __half g_h[(size_t)NSLOT * HIDDEN];             // hidden acts fp16

__device__ __forceinline__ float gelu_exact(float v) {
    return 0.5f * v * (1.0f + erff(v * 0.70710678118654752440f));
}

// ---------------- PTX helpers ----------------
__device__ __forceinline__ uint32_t smem_u32(const void* p) {
    uint32_t a;
    asm("{ .reg .u64 t; cvta.to.shared.u64 t, %1; cvt.u32.u64 %0, t; }" : "=r"(a) : "l"(p));
    return a;
}
__device__ __forceinline__ void cp16(uint32_t dst, const void* src) {
    asm volatile("cp.async.cg.shared.global [%0], [%1], 16;\n" :: "r"(dst), "l"(src) : "memory");
}
#define CP_COMMIT() asm volatile("cp.async.commit_group;\n" ::: "memory")
template<int N> __device__ __forceinline__ void cp_wait() {
    asm volatile("cp.async.wait_group %0;\n" :: "n"(N) : "memory");
}
__device__ __forceinline__ void ldsm4(uint32_t& r0, uint32_t& r1, uint32_t& r2, uint32_t& r3,
                                      uint32_t addr) {
    asm volatile("ldmatrix.sync.aligned.m8n8.x4.shared.b16 {%0,%1,%2,%3}, [%4];"
                 : "=r"(r0), "=r"(r1), "=r"(r2), "=r"(r3) : "r"(addr));
}
__device__ __forceinline__ void mma_f16(float* d, const uint32_t* a, const uint32_t* b) {
    asm volatile(
        "mma.sync.aligned.m16n8k16.row.col.f32.f16.f16.f32 "
        "{%0,%1,%2,%3}, {%4,%5,%6,%7}, {%8,%9}, {%0,%1,%2,%3};"
        : "+f"(d[0]), "+f"(d[1]), "+f"(d[2]), "+f"(d[3])
        : "r"(a[0]), "r"(a[1]), "r"(a[2]), "r"(a[3]), "r"(b[0]), "r"(b[1]));
}

// ---------------- small kernels ----------------
__global__ void zero_kernel() {
    if (threadIdx.x < NEXP) g_cnt[threadIdx.x] = 0;
}

// router; also converts x -> fp16 (fused, reuses the loaded values)
__global__ void router_kernel(const float* __restrict__ x,
                              const float* __restrict__ rW,
                              const float* __restrict__ rb) {
    const int t = blockIdx.x, tid = threadIdx.x;
    __shared__ float sg[128][NEXP];
    float acc[NEXP];
    #pragma unroll
    for (int e = 0; e < NEXP; e++) acc[e] = 0.0f;
    const float* xr = x + (size_t)t * D_MODEL;
    __half* xh = g_xh + (size_t)t * D_MODEL;
    for (int d = tid; d < D_MODEL; d += 128) {
        const float xv = xr[d];
        xh[d] = __float2half_rn(xv);
        const float* r = rW + (size_t)d * NEXP;
        #pragma unroll
        for (int e = 0; e < NEXP; e++) acc[e] += xv * r[e];
    }
    #pragma unroll
    for (int e = 0; e < NEXP; e++) sg[tid][e] = acc[e];
    __syncthreads();
    if (tid < NEXP) {
        float s = rb[tid];
        for (int i = 0; i < 128; i++) s += sg[i][tid];
        sg[0][tid] = s;
    }
    __syncthreads();
    if (tid == 0) {
        float g[NEXP];
        #pragma unroll
        for (int e = 0; e < NEXP; e++) g[e] = sg[0][e];
        int e0 = 0;
        #pragma unroll
        for (int e = 1; e < NEXP; e++) if (g[e] > g[e0]) e0 = e;
        int e1 = (e0 == 0) ? 1 : 0;
        #pragma unroll
        for (int e = 0; e < NEXP; e++) if (e != e0 && g[e] > g[e1]) e1 = e;
        const float p1 = expf(g[e1] - g[e0]);
        const float inv = 1.0f / (1.0f + p1);
        const float w0 = inv, w1 = p1 * inv;
        g_tok_e[t][0] = e0; g_tok_e[t][1] = e1;
        g_tok_w[t][0] = w0; g_tok_w[t][1] = w1;
        int p = atomicAdd(&g_cnt[e0], 1);
        g_slot_tok[e0][p] = t; g_slot_w[e0][p] = w0;
        p = atomicAdd(&g_cnt[e1], 1);
        g_slot_tok[e1][p] = t; g_slot_w[e1][p] = w1;
    }
}

__global__ void init_out_kernel(float* __restrict__ out,
                                const float* __restrict__ b2,
                                const float* __restrict__ sb2) {
    const int idx = blockIdx.x * 256 + threadIdx.x;
    if (idx >= NTOK * D_MODEL) return;
    const int t = idx >> 10, d = idx & 1023;
    float v = 0.5f * (sb2[d] + sb2[D_MODEL + d]);
    v += g_tok_w[t][0] * b2[(size_t)g_tok_e[t][0] * D_MODEL + d];
    v += g_tok_w[t][1] * b2[(size_t)g_tok_e[t][1] * D_MODEL + d];
    out[idx] = v;
}

// [z][R][C] fp32 -> [z][C][R] fp16. dst resolved in DEVICE code.
__global__ void transp_kernel(const float* __restrict__ srcR, const float* __restrict__ srcS,
                              int which, int R, int C) {
    __half* __restrict__ dst0 = which ? g_w2t : g_w1t;
    const int z = blockIdx.z;
    const float* src = (z < NEXP) ? srcR + (size_t)z * R * C : srcS + (size_t)(z - NEXP) * R * C;
    __half* d = dst0 + (size_t)z * R * C;
    __shared__ float tile[32][33];
    const int c0 = blockIdx.x * 32, r0 = blockIdx.y * 32;
    const int tx = threadIdx.x, ty = threadIdx.y;
    #pragma unroll
    for (int q = 0; q < 4; q++)
        tile[ty + 8 * q][tx] = src[(size_t)(r0 + ty + 8 * q) * C + c0 + tx];
    __syncthreads();
    #pragma unroll
    for (int q = 0; q < 4; q++)
        d[(size_t)(c0 + ty + 8 * q) * R + r0 + tx] = __float2half_rn(tile[tx][ty + 8 * q]);
}

// ---------------- fp16 mma grouped GEMM: R11 core + warp-phase stagger ----------------
#define BM 128
#define BN 128
#define BK 32
#define STAGE_B 16384           // 8KB A + 8KB B; 3 stages = 48KB static

__device__ __forceinline__ uint32_t swz(int row, int q) {
    return (uint32_t)(row * 64 + ((q ^ ((row >> 1) & 3)) << 4));
}

template<int KTOT, bool G1>
__global__ __launch_bounds__(256, 2) void moe_mma(
    const float* __restrict__ bias_r, const float* __restrict__ bias_s,
    float* __restrict__ out)
{
    constexpr int NC = KTOT / BK;
    const int z = blockIdx.z;

    int cnt, hbase;
    if (z < NEXP) {
        cnt = g_cnt[z];
        int b = 0;
        #pragma unroll
        for (int e = 0; e < NEXP; e++) if (e < z) b += g_cnt[e];
        hbase = b;
    } else {
        cnt = NTOK;
        hbase = 8192 + (z - NEXP) * NTOK;
    }

    const int m0 = blockIdx.x * BM;
    if (m0 >= cnt) return;
    const int n0 = blockIdx.y * BN;

    __shared__ __align__(1024) uint8_t smbuf[3 * STAGE_B];
    const uint32_t sb = smem_u32(smbuf);

    const int tid = threadIdx.x, lane = tid & 31, wid = tid >> 5;
    const int wm = (wid & 1) * 64, wn = (wid >> 1) * 32;
    // phase stagger: warps {0-3} vs {4-7} — each SMSP hosts one of each,
    // so one warp MMAs while its SMSP sibling does LDSM.
    const int kkph = (wid >> 2) & 1;

    // ---- loader plan: thread -> rows (lr, lr+64), one 16B quad lq ----
    const int lr = tid >> 2, lq = tid & 3;
    const __half* asrc0;
    const __half* asrc1;
    if (G1) {
        int t0, t1;
        if (z < NEXP) {
            const int i0 = m0 + lr, i1 = m0 + lr + 64;
            t0 = g_slot_tok[z][i0 < cnt ? i0 : cnt - 1];
            t1 = g_slot_tok[z][i1 < cnt ? i1 : cnt - 1];
        } else { t0 = m0 + lr; t1 = m0 + lr + 64; }
        asrc0 = g_xh + (size_t)t0 * D_MODEL + lq * 8;
        asrc1 = g_xh + (size_t)t1 * D_MODEL + lq * 8;
    } else {
        asrc0 = g_h + (size_t)(hbase + m0 + lr) * HIDDEN + lq * 8;
        asrc1 = g_h + (size_t)(hbase + m0 + lr + 64) * HIDDEN + lq * 8;
    }
    const __half* Bt = (G1 ? g_w1t : g_w2t) + (size_t)z * D_MODEL * HIDDEN;
    const __half* bsrc0 = Bt + (size_t)(n0 + lr) * KTOT + lq * 8;
    const __half* bsrc1 = Bt + (size_t)(n0 + lr + 64) * KTOT + lq * 8;

    const uint32_t dA0 = swz(lr, lq), dA1 = swz(lr + 64, lq);
    const uint32_t dB0 = 8192u + dA0, dB1 = 8192u + dA1;

    // ---- fragment lane constants ----
    const int g  = lane >> 3, rin = lane & 7;
    const int gl = g & 1, gh = g >> 1;
    uint32_t aRow[4]; int aF[4];
    #pragma unroll
    for (int mt = 0; mt < 4; mt++) {
        const int r = wm + mt * 16 + gl * 8 + rin;
        aRow[mt] = (uint32_t)(r * 64);
        aF[mt]   = (r >> 1) & 3;
    }
    uint32_t bRow[2]; int bF[2];
    #pragma unroll
    for (int p = 0; p < 2; p++) {
        const int r = wn + p * 16 + gh * 8 + rin;
        bRow[p] = 8192u + (uint32_t)(r * 64);
        bF[p]   = (r >> 1) & 3;
    }

    float acc[4][4][4];
    #pragma unroll
    for (int mt = 0; mt < 4; mt++)
        #pragma unroll
        for (int nt = 0; nt < 4; nt++)
            #pragma unroll
            for (int q = 0; q < 4; q++) acc[mt][nt][q] = 0.0f;

    auto load_chunk = [&](int c, int s) {
        const uint32_t st = sb + (uint32_t)s * STAGE_B;
        const int ko = c * BK;
        cp16(st + dA0, asrc0 + ko);
        cp16(st + dA1, asrc1 + ko);
        cp16(st + dB0, bsrc0 + ko);
        cp16(st + dB1, bsrc1 + ko);
        CP_COMMIT();
    };

    load_chunk(0, 0);
    load_chunk(1, 1);

    int s = 0, s2 = 2;
    #pragma unroll 1
    for (int c = 0; c < NC; c++) {
        if (c + 1 < NC) cp_wait<1>(); else cp_wait<0>();
        __syncthreads();
        if (c + 2 < NC) load_chunk(c + 2, s2);

        const uint32_t st = sb + (uint32_t)s * STAGE_B;
        #pragma unroll
        for (int kki = 0; kki < 2; kki++) {
            const int kk = kki ^ kkph;      // stagger LDSM/MMA phases across SMSP siblings
            uint32_t a[4][4], b[4][2];
            #pragma unroll
            for (int mt = 0; mt < 4; mt++)
                ldsm4(a[mt][0], a[mt][1], a[mt][2], a[mt][3],
                      st + aRow[mt] + (uint32_t)(((2 * kk + gh) ^ aF[mt]) << 4));
            {
                uint32_t r0, r1, r2, r3;
                ldsm4(r0, r1, r2, r3, st + bRow[0] + (uint32_t)(((2 * kk + gl) ^ bF[0]) << 4));
                b[0][0] = r0; b[0][1] = r1; b[1][0] = r2; b[1][1] = r3;
                ldsm4(r0, r1, r2, r3, st + bRow[1] + (uint32_t)(((2 * kk + gl) ^ bF[1]) << 4));
                b[2][0] = r0; b[2][1] = r1; b[3][0] = r2; b[3][1] = r3;
            }
            #pragma unroll
            for (int mt = 0; mt < 4; mt++)
                #pragma unroll
                for (int nt = 0; nt < 4; nt++)
                    mma_f16(acc[mt][nt], a[mt], b[nt]);
        }
        s = (s == 2) ? 0 : s + 1;
        s2 = (s2 == 2) ? 0 : s2 + 1;
    }

    // ---------------- epilogue (C frag: rows fr(+8), cols 2*fc(+1)) ----------------
    const int fr = lane >> 2, fc = lane & 3;
    if (G1) {
        const float* bias = (z < NEXP) ? bias_r + (size_t)z * HIDDEN + n0
                                       : bias_s + (size_t)(z - NEXP) * HIDDEN + n0;
        #pragma unroll
        for (int mt = 0; mt < 4; mt++) {
            #pragma unroll
            for (int h2 = 0; h2 < 2; h2++) {
                const int mloc = wm + mt * 16 + fr + 8 * h2;
                if (m0 + mloc < cnt) {
                    __half* hrow = g_h + (size_t)(hbase + m0 + mloc) * HIDDEN + n0;
                    #pragma unroll
                    for (int nt = 0; nt < 4; nt++) {
                        const int col = wn + nt * 8 + 2 * fc;
                        const float v0 = gelu_exact(acc[mt][nt][2 * h2]     + bias[col]);
                        const float v1 = gelu_exact(acc[mt][nt][2 * h2 + 1] + bias[col + 1]);
                        *(__half2*)(hrow + col) = __floats2half2_rn(v0, v1);
                    }
                }
            }
        }
    } else {
        #pragma unroll
        for (int mt = 0; mt < 4; mt++) {
            #pragma unroll
            for (int h2 = 0; h2 < 2; h2++) {
                const int mloc = wm + mt * 16 + fr + 8 * h2;
                const int m = m0 + mloc;
                if (m < cnt) {
                    int t; float w;
                    if (z < NEXP) { t = g_slot_tok[z][m]; w = g_slot_w[z][m]; }
                    else          { t = m; w = 0.5f; }
                    float* orow = out + (size_t)t * D_MODEL + n0;
                    #pragma unroll
                    for (int nt = 0; nt < 4; nt++) {
                        const int col = wn + nt * 8 + 2 * fc;
                        atomicAdd(orow + col,     w * acc[mt][nt][2 * h2]);
                        atomicAdd(orow + col + 1, w * acc[mt][nt][2 * h2 + 1]);
                    }
                }
            }
        }
    }
}

// ---------------- launch ----------------
extern "C" void kernel_launch(void* const* d_in, const int* in_sizes, int n_in,
                              void* d_out, int out_size) {
    (void)in_sizes; (void)n_in; (void)out_size;
    const float* x   = (const float*)d_in[0];
    const float* rW  = (const float*)d_in[1];
    const float* rb  = (const float*)d_in[2];
    const float* W1  = (const float*)d_in[3];
    const float* b1  = (const float*)d_in[4];
    const float* W2  = (const float*)d_in[5];
    const float* b2  = (const float*)d_in[6];
    const float* sW1 = (const float*)d_in[7];
    const float* sb1 = (const float*)d_in[8];
    const float* sW2 = (const float*)d_in[9];
    const float* sb2 = (const float*)d_in[10];
    float* out = (float*)d_out;

    // moe_mma<G1> kept as the 4th launch (ncu capture slot)
    zero_kernel<<<1, 32>>>();                                             // 1
    router_kernel<<<NTOK, 128>>>(x, rW, rb);                              // 2 (also x->fp16)
    transp_kernel<<<dim3(HIDDEN / 32, D_MODEL / 32, NZ), dim3(32, 8)>>>(  // 3
        W1, sW1, 0, D_MODEL, HIDDEN);
    moe_mma<D_MODEL, true><<<dim3(CAP / BM, HIDDEN / BN, NZ), 256>>>(     // 4
        b1, sb1, nullptr);
    transp_kernel<<<dim3(D_MODEL / 32, HIDDEN / 32, NZ), dim3(32, 8)>>>(  // 5
        W2, sW2, 1, HIDDEN, D_MODEL);
    init_out_kernel<<<(NTOK * D_MODEL) / 256, 256>>>(out, b2, sb2);       // 6
    moe_mma<HIDDEN, false><<<dim3(CAP / BM, D_MODEL / BN, NZ), 256>>>(    // 7
        nullptr, nullptr, out);
}